// round 9
// baseline (speedup 1.0000x reference)
#include <cuda_runtime.h>
#include <cuda_bf16.h>

// Problem constants
#define CH   64
#define HW   1296
#define NTOT (CH * HW)   // 82944
#define LOG2E 1.4426950408889634f

#define SEGS 6            // j-segments per attn block
#define OPB  32           // outputs per attn block (= warp width)
#define J4   (HW / 4)     // 324 float4 per channel row
#define JSEG (J4 / SEGS)  // 54 float4 per segment

typedef unsigned long long u64;

// Scratch (device globals; float4 forces 16B alignment)
__device__ float4 g_q4 [NTOT / 4];
__device__ float4 g_k4 [NTOT / 4];   // k * log2e (SoA)
__device__ float4 g_v4 [NTOT / 4];   // v         (SoA)
__device__ float4 g_yp4[NTOT / 4];

__device__ __forceinline__ float ex2f(float x) {
    float r;
    asm("ex2.approx.f32 %0, %1;" : "=f"(r) : "f"(x));
    return r;
}
// FMA-pipe exp2: round via magic constant, deg-4 Horner, exponent insert.
// |arg| < ~45 here; rel err ~4e-5 (on 1/8 of softmax terms -> ~5e-6 output).
__device__ __forceinline__ float ex2p(float a) {
    float t = a + 12582912.0f;            // 2^23 + 2^22: n in mantissa
    float f = a - (t - 12582912.0f);      // f in [-0.5, 0.5]
    float p = 0.0096181291f;
    p = fmaf(p, f, 0.0555041087f);
    p = fmaf(p, f, 0.2402265069f);
    p = fmaf(p, f, 0.6931471806f);
    p = fmaf(p, f, 1.0f);
    return __int_as_float(__float_as_int(p) + (__float_as_int(t) << 23));
}
__device__ __forceinline__ u64 pack2(float lo, float hi) {
    u64 r; asm("mov.b64 %0, {%1, %2};" : "=l"(r) : "f"(lo), "f"(hi)); return r;
}
__device__ __forceinline__ void unpack2(float& lo, float& hi, u64 v) {
    asm("mov.b64 {%0, %1}, %2;" : "=f"(lo), "=f"(hi) : "l"(v));
}
__device__ __forceinline__ u64 mul2(u64 a, u64 b) {
    u64 r; asm("mul.rn.f32x2 %0, %1, %2;" : "=l"(r) : "l"(a), "l"(b)); return r;
}
__device__ __forceinline__ void adda2(u64& d, u64 a) {
    asm("add.rn.f32x2 %0, %1, %0;" : "+l"(d) : "l"(a));
}
__device__ __forceinline__ void fma2(u64& d, u64 a, u64 b) {
    asm("fma.rn.f32x2 %0, %1, %2, %0;" : "+l"(d) : "l"(a), "l"(b));
}

// ---------------------------------------------------------------------------
// Kernel A: pair-fused 1x1-conv projections, TWO o-values per thread.
//   pair 0: q & k from x ; pair 1: v & yp from y.
// Each thread: (pair, o-pair, 4 pixels) -> pixel L2 traffic halves vs R7
// (each pixel quad read once per 2 output channels): 21 MB total.
// 20736 threads = 162 blocks x 128; 8 independent LDG.128/iter keeps MLP
// high enough to cover L2 latency at low occupancy (BW-bound regime).
// ---------------------------------------------------------------------------
__global__ void proj_kernel(const float* __restrict__ x,
                            const float* __restrict__ y,
                            const float* __restrict__ Wq, const float* __restrict__ bq,
                            const float* __restrict__ Wk, const float* __restrict__ bk,
                            const float* __restrict__ Wv, const float* __restrict__ bv,
                            const float* __restrict__ Wp) {
    int g    = blockIdx.x * 128 + threadIdx.x;   // 0 .. 20735
    int pair = g / (NTOT / 8);                   // 0: q,k   1: v,yp
    int r    = g - pair * (NTOT / 8);
    int op   = r / (HW / 4);                     // o-pair: o = 2*op, 2*op+1
    int i    = (r - op * (HW / 4)) * 4;          // pixel base
    int o1   = op * 2, o2 = op * 2 + 1;

    const float* src;
    const float* W1;
    const float* W2;
    float b1a, b1b, b2a, b2b;
    if (pair == 0) {
        src = x; W1 = Wq; W2 = Wk;
        b1a = __ldg(&bq[o1]); b1b = __ldg(&bq[o2]);
        b2a = __ldg(&bk[o1]); b2b = __ldg(&bk[o2]);
    } else {
        src = y; W1 = Wv; W2 = Wp;
        b1a = __ldg(&bv[o1]); b1b = __ldg(&bv[o2]);
        b2a = 0.0f;           b2b = 0.0f;
    }

    float4 a1a = make_float4(b1a, b1a, b1a, b1a);   // proj1, o1
    float4 a1b = make_float4(b1b, b1b, b1b, b1b);   // proj1, o2
    float4 a2a = make_float4(b2a, b2a, b2a, b2a);   // proj2, o1
    float4 a2b = make_float4(b2b, b2b, b2b, b2b);   // proj2, o2

    const float4* W1a = reinterpret_cast<const float4*>(W1 + o1 * CH);
    const float4* W1b = reinterpret_cast<const float4*>(W1 + o2 * CH);
    const float4* W2a = reinterpret_cast<const float4*>(W2 + o1 * CH);
    const float4* W2b = reinterpret_cast<const float4*>(W2 + o2 * CH);

    #pragma unroll 4
    for (int cg = 0; cg < CH / 4; cg++) {
        float4 w1a = __ldg(&W1a[cg]);
        float4 w1b = __ldg(&W1b[cg]);
        float4 w2a = __ldg(&W2a[cg]);
        float4 w2b = __ldg(&W2b[cg]);
        const float* s0 = src + (cg * 4) * HW + i;
        float4 p0 = *reinterpret_cast<const float4*>(s0);
        float4 p1 = *reinterpret_cast<const float4*>(s0 + HW);
        float4 p2 = *reinterpret_cast<const float4*>(s0 + 2 * HW);
        float4 p3 = *reinterpret_cast<const float4*>(s0 + 3 * HW);

        a1a.x = fmaf(w1a.x, p0.x, a1a.x); a1a.y = fmaf(w1a.x, p0.y, a1a.y);
        a1a.z = fmaf(w1a.x, p0.z, a1a.z); a1a.w = fmaf(w1a.x, p0.w, a1a.w);
        a1a.x = fmaf(w1a.y, p1.x, a1a.x); a1a.y = fmaf(w1a.y, p1.y, a1a.y);
        a1a.z = fmaf(w1a.y, p1.z, a1a.z); a1a.w = fmaf(w1a.y, p1.w, a1a.w);
        a1a.x = fmaf(w1a.z, p2.x, a1a.x); a1a.y = fmaf(w1a.z, p2.y, a1a.y);
        a1a.z = fmaf(w1a.z, p2.z, a1a.z); a1a.w = fmaf(w1a.z, p2.w, a1a.w);
        a1a.x = fmaf(w1a.w, p3.x, a1a.x); a1a.y = fmaf(w1a.w, p3.y, a1a.y);
        a1a.z = fmaf(w1a.w, p3.z, a1a.z); a1a.w = fmaf(w1a.w, p3.w, a1a.w);

        a1b.x = fmaf(w1b.x, p0.x, a1b.x); a1b.y = fmaf(w1b.x, p0.y, a1b.y);
        a1b.z = fmaf(w1b.x, p0.z, a1b.z); a1b.w = fmaf(w1b.x, p0.w, a1b.w);
        a1b.x = fmaf(w1b.y, p1.x, a1b.x); a1b.y = fmaf(w1b.y, p1.y, a1b.y);
        a1b.z = fmaf(w1b.y, p1.z, a1b.z); a1b.w = fmaf(w1b.y, p1.w, a1b.w);
        a1b.x = fmaf(w1b.z, p2.x, a1b.x); a1b.y = fmaf(w1b.z, p2.y, a1b.y);
        a1b.z = fmaf(w1b.z, p2.z, a1b.z); a1b.w = fmaf(w1b.z, p2.w, a1b.w);
        a1b.x = fmaf(w1b.w, p3.x, a1b.x); a1b.y = fmaf(w1b.w, p3.y, a1b.y);
        a1b.z = fmaf(w1b.w, p3.z, a1b.z); a1b.w = fmaf(w1b.w, p3.w, a1b.w);

        a2a.x = fmaf(w2a.x, p0.x, a2a.x); a2a.y = fmaf(w2a.x, p0.y, a2a.y);
        a2a.z = fmaf(w2a.x, p0.z, a2a.z); a2a.w = fmaf(w2a.x, p0.w, a2a.w);
        a2a.x = fmaf(w2a.y, p1.x, a2a.x); a2a.y = fmaf(w2a.y, p1.y, a2a.y);
        a2a.z = fmaf(w2a.y, p1.z, a2a.z); a2a.w = fmaf(w2a.y, p1.w, a2a.w);
        a2a.x = fmaf(w2a.z, p2.x, a2a.x); a2a.y = fmaf(w2a.z, p2.y, a2a.y);
        a2a.z = fmaf(w2a.z, p2.z, a2a.z); a2a.w = fmaf(w2a.z, p2.w, a2a.w);
        a2a.x = fmaf(w2a.w, p3.x, a2a.x); a2a.y = fmaf(w2a.w, p3.y, a2a.y);
        a2a.z = fmaf(w2a.w, p3.z, a2a.z); a2a.w = fmaf(w2a.w, p3.w, a2a.w);

        a2b.x = fmaf(w2b.x, p0.x, a2b.x); a2b.y = fmaf(w2b.x, p0.y, a2b.y);
        a2b.z = fmaf(w2b.x, p0.z, a2b.z); a2b.w = fmaf(w2b.x, p0.w, a2b.w);
        a2b.x = fmaf(w2b.y, p1.x, a2b.x); a2b.y = fmaf(w2b.y, p1.y, a2b.y);
        a2b.z = fmaf(w2b.y, p1.z, a2b.z); a2b.w = fmaf(w2b.y, p1.w, a2b.w);
        a2b.x = fmaf(w2b.z, p2.x, a2b.x); a2b.y = fmaf(w2b.z, p2.y, a2b.y);
        a2b.z = fmaf(w2b.z, p2.z, a2b.z); a2b.w = fmaf(w2b.z, p2.w, a2b.w);
        a2b.x = fmaf(w2b.w, p3.x, a2b.x); a2b.y = fmaf(w2b.w, p3.y, a2b.y);
        a2b.z = fmaf(w2b.w, p3.z, a2b.z); a2b.w = fmaf(w2b.w, p3.w, a2b.w);
    }

    int idxa = (o1 * HW + i) >> 2;
    int idxb = (o2 * HW + i) >> 2;
    if (pair == 0) {
        g_q4[idxa] = a1a;
        g_q4[idxb] = a1b;
        g_k4[idxa] = make_float4(a2a.x * LOG2E, a2a.y * LOG2E,
                                 a2a.z * LOG2E, a2a.w * LOG2E);
        g_k4[idxb] = make_float4(a2b.x * LOG2E, a2b.y * LOG2E,
                                 a2b.z * LOG2E, a2b.w * LOG2E);
    } else {
        g_v4[idxa]  = a1a;
        g_v4[idxb]  = a1b;
        g_yp4[idxa] = a2a;
        g_yp4[idxb] = a2b;
    }
}

// ---------------------------------------------------------------------------
// Kernel B: attention + gated residual.
// One block = one channel x 32 outputs x 6 j-segments (192 threads).
// k/v staged in smem (warp-uniform LDS.128 broadcast). MUFU saturated
// (R6/R7 invariance at ~45.4k cyc) -> offload exactly 1 exp in 8 to the
// FMA-pipe poly ex2p, on a DECOUPLED scalar accumulator stream so its
// latency chain never gates the packed-f32x2 accumulation (R8's mistake).
// Shiftless softmax: |q.k| << 88 by construction; ratio is scale-invariant.
// ---------------------------------------------------------------------------
__global__ void attn_kernel(const float* __restrict__ gamma,
                            float* __restrict__ out) {
    __shared__ ulonglong2 ks2[J4];    // 4 packed k*log2e per entry
    __shared__ ulonglong2 vs2[J4];
    __shared__ float2 part[SEGS * OPB];

    int c  = blockIdx.y;
    int i0 = blockIdx.x * OPB;
    int t  = threadIdx.x;          // 0..191
    int il = t & 31;               // lane -> output
    int seg = t >> 5;              // warp -> j-segment (uniform per warp)

    const ulonglong2* gk = reinterpret_cast<const ulonglong2*>(&g_k4[c * J4]);
    const ulonglong2* gv = reinterpret_cast<const ulonglong2*>(&g_v4[c * J4]);
    for (int idx = t; idx < J4; idx += SEGS * OPB) {
        ks2[idx] = gk[idx];
        vs2[idx] = gv[idx];
    }
    __syncthreads();

    int i = i0 + il;
    bool valid = (i < HW);
    float s = reinterpret_cast<const float*>(g_q4)[c * HW + (valid ? i : 0)];
    u64 s2 = pack2(s, s);

    int j0 = seg * JSEG;
    u64 d01 = 0, d23 = 0, n01 = 0, n23 = 0;   // packed streams (elems 0-5)
    float ds = 0.0f, ns = 0.0f;               // scalar MUFU stream (elem 6)
    float dp = 0.0f, np = 0.0f;               // poly stream (elem 7)
    #pragma unroll 3
    for (int j = j0; j < j0 + JSEG; j += 2) {  // 8 exps per iteration
        ulonglong2 ka = ks2[j];
        ulonglong2 kb = ks2[j + 1];
        ulonglong2 va = vs2[j];
        ulonglong2 vb = vs2[j + 1];
        u64 a01 = mul2(ka.x, s2);
        u64 a23 = mul2(ka.y, s2);
        u64 a45 = mul2(kb.x, s2);
        float f0, f1, f2, f3, f4, f5, k6, k7, v6, v7;
        unpack2(f0, f1, a01);
        unpack2(f2, f3, a23);
        unpack2(f4, f5, a45);
        unpack2(k6, k7, kb.y);
        unpack2(v6, v7, vb.y);
        u64 t01 = pack2(ex2f(f0), ex2f(f1));
        u64 t23 = pack2(ex2f(f2), ex2f(f3));
        u64 t45 = pack2(ex2f(f4), ex2f(f5));
        float t6 = ex2f(s * k6);
        float t7 = ex2p(s * k7);               // decoupled FMA-pipe exp
        adda2(d01, t01); fma2(n01, t01, va.x);
        adda2(d23, t23); fma2(n23, t23, va.y);
        adda2(d01, t45); fma2(n01, t45, vb.x);
        ds += t6; ns = fmaf(t6, v6, ns);
        dp += t7; np = fmaf(t7, v7, np);
    }

    float a, b, e, f;
    unpack2(a, b, d01); unpack2(e, f, d23);
    float dsum = ((a + b) + (e + f)) + (ds + dp);
    unpack2(a, b, n01); unpack2(e, f, n23);
    float nsum = ((a + b) + (e + f)) + (ns + np);

    part[t] = make_float2(dsum, nsum);
    __syncthreads();

    if (seg == 0 && valid) {
        float dd = 0.0f, nn = 0.0f;
        #pragma unroll
        for (int ss = 0; ss < SEGS; ss++) {
            float2 p = part[ss * OPB + il];
            dd += p.x; nn += p.y;
        }
        float gm = __ldg(&gamma[0]);
        float yp = reinterpret_cast<const float*>(g_yp4)[c * HW + i];
        out[c * HW + i] = (gm * (nn / dd) + yp) / (1.0f + gm);
    }
}

// ---------------------------------------------------------------------------
extern "C" void kernel_launch(void* const* d_in, const int* in_sizes, int n_in,
                              void* d_out, int out_size) {
    const float* x     = (const float*)d_in[0];
    const float* y     = (const float*)d_in[1];
    const float* Wq    = (const float*)d_in[2];
    const float* bq    = (const float*)d_in[3];
    const float* Wk    = (const float*)d_in[4];
    const float* bk    = (const float*)d_in[5];
    const float* Wv    = (const float*)d_in[6];
    const float* bv    = (const float*)d_in[7];
    const float* Wp    = (const float*)d_in[8];
    const float* gamma = (const float*)d_in[9];
    float* out = (float*)d_out;

    proj_kernel<<<(NTOT / 4) / 128, 128>>>(x, y, Wq, bq, Wk, bk, Wv, bv, Wp);

    dim3 agrid((HW + OPB - 1) / OPB, CH);  // (41, 64)
    attn_kernel<<<agrid, SEGS * OPB>>>(gamma, out);
}

// round 10
// speedup vs baseline: 1.5222x; 1.5222x over previous
#include <cuda_runtime.h>
#include <cuda_bf16.h>

// Problem constants
#define CH   64
#define HW   1296
#define NTOT (CH * HW)   // 82944

#define NM      58        // moments m = 0..57
#define MPAIRS  29        // computed as (even, odd) pairs
#define JHALF   648       // j's per moment half-block
#define JCHUNK  81        // j's per moment thread

// Scratch (device globals; float4 forces 16B alignment)
__device__ float4 g_q4 [NTOT / 4];
__device__ float4 g_k4 [NTOT / 4];
__device__ float4 g_v4 [NTOT / 4];
__device__ float4 g_yp4[NTOT / 4];
__device__ float  g_CS[CH][2][64];   // Σ_j τ^m/m!        (denominator moments)
__device__ float  g_CM[CH][2][64];   // Σ_j τ^m/m! v_j    (numerator moments)
__device__ float  g_qmax[CH];

__device__ __forceinline__ float ex2f(float x) {
    float r;
    asm("ex2.approx.f32 %0, %1;" : "=f"(r) : "f"(x));
    return r;
}

// ---------------------------------------------------------------------------
// Kernel A: pair-fused 1x1-conv projections (R7 structure; best measured).
//   pair 0: q & k from x (x loaded once for both) ; pair 1: v & yp from y.
// ---------------------------------------------------------------------------
__global__ void proj_kernel(const float* __restrict__ x,
                            const float* __restrict__ y,
                            const float* __restrict__ Wq, const float* __restrict__ bq,
                            const float* __restrict__ Wk, const float* __restrict__ bk,
                            const float* __restrict__ Wv, const float* __restrict__ bv,
                            const float* __restrict__ Wp) {
    int g    = blockIdx.x * 128 + threadIdx.x;   // 0 .. 41471
    int pair = g / (NTOT / 4);                   // 0: q,k   1: v,yp
    int r    = g - pair * (NTOT / 4);
    int o    = r / (HW / 4);                     // out channel
    int i    = (r - o * (HW / 4)) * 4;           // pixel base

    const float* src;
    const float* W1;
    const float* W2;
    float b1, b2;
    if (pair == 0) { src = x; W1 = Wq; W2 = Wk; b1 = __ldg(&bq[o]); b2 = __ldg(&bk[o]); }
    else           { src = y; W1 = Wv; W2 = Wp; b1 = __ldg(&bv[o]); b2 = 0.0f; }

    float4 a1 = make_float4(b1, b1, b1, b1);
    float4 a2 = make_float4(b2, b2, b2, b2);
    const float4* W14 = reinterpret_cast<const float4*>(W1 + o * CH);
    const float4* W24 = reinterpret_cast<const float4*>(W2 + o * CH);

    #pragma unroll 4
    for (int cg = 0; cg < CH / 4; cg++) {
        float4 w1 = __ldg(&W14[cg]);
        float4 w2 = __ldg(&W24[cg]);
        const float* s0 = src + (cg * 4) * HW + i;
        float4 p0 = *reinterpret_cast<const float4*>(s0);
        float4 p1 = *reinterpret_cast<const float4*>(s0 + HW);
        float4 p2 = *reinterpret_cast<const float4*>(s0 + 2 * HW);
        float4 p3 = *reinterpret_cast<const float4*>(s0 + 3 * HW);

        a1.x = fmaf(w1.x, p0.x, a1.x); a1.y = fmaf(w1.x, p0.y, a1.y);
        a1.z = fmaf(w1.x, p0.z, a1.z); a1.w = fmaf(w1.x, p0.w, a1.w);
        a1.x = fmaf(w1.y, p1.x, a1.x); a1.y = fmaf(w1.y, p1.y, a1.y);
        a1.z = fmaf(w1.y, p1.z, a1.z); a1.w = fmaf(w1.y, p1.w, a1.w);
        a1.x = fmaf(w1.z, p2.x, a1.x); a1.y = fmaf(w1.z, p2.y, a1.y);
        a1.z = fmaf(w1.z, p2.z, a1.z); a1.w = fmaf(w1.z, p2.w, a1.w);
        a1.x = fmaf(w1.w, p3.x, a1.x); a1.y = fmaf(w1.w, p3.y, a1.y);
        a1.z = fmaf(w1.w, p3.z, a1.z); a1.w = fmaf(w1.w, p3.w, a1.w);

        a2.x = fmaf(w2.x, p0.x, a2.x); a2.y = fmaf(w2.x, p0.y, a2.y);
        a2.z = fmaf(w2.x, p0.z, a2.z); a2.w = fmaf(w2.x, p0.w, a2.w);
        a2.x = fmaf(w2.y, p1.x, a2.x); a2.y = fmaf(w2.y, p1.y, a2.y);
        a2.z = fmaf(w2.y, p1.z, a2.z); a2.w = fmaf(w2.y, p1.w, a2.w);
        a2.x = fmaf(w2.z, p2.x, a2.x); a2.y = fmaf(w2.z, p2.y, a2.y);
        a2.z = fmaf(w2.z, p2.z, a2.z); a2.w = fmaf(w2.z, p2.w, a2.w);
        a2.x = fmaf(w2.w, p3.x, a2.x); a2.y = fmaf(w2.w, p3.y, a2.y);
        a2.z = fmaf(w2.w, p3.z, a2.z); a2.w = fmaf(w2.w, p3.w, a2.w);
    }

    int idx4 = (o * HW + i) >> 2;
    if (pair == 0) {
        g_q4[idx4] = a1;
        g_k4[idx4] = a2;          // raw k (natural-exp Taylor downstream)
    } else {
        g_v4[idx4]  = a1;
        g_yp4[idx4] = a2;
    }
}

// ---------------------------------------------------------------------------
// Kernel B: per-channel scaled exponential moments.
//   tau_j = k_j * Qmax_c ;  CS_m = sum_j tau^m/m! ;  CM_m = sum_j tau^m/m! v_j
// Grid (2 halves, 64 channels), 256 threads: thread = (m-pair 0..28, chunk 0..7).
// Powers via ex2(m*log2|tau| - log2 m!) for even m (sign +); odd m derived by
// one multiply with the SIGNED tau (automatic sign, /(m+1) folded).
// ---------------------------------------------------------------------------
__global__ void moments_kernel() {
    __shared__ float tau_s[JHALF];
    __shared__ float lt_s [JHALF];
    __shared__ float v_s  [JHALF];
    __shared__ float qmax_s[256];
    __shared__ float red[MPAIRS][8][4];

    int c    = blockIdx.y;
    int half = blockIdx.x;
    int t    = threadIdx.x;

    // Phase 1: Qmax over the full channel's q row
    const float* q = reinterpret_cast<const float*>(g_q4) + c * HW;
    float mx = 0.0f;
    for (int i = t; i < HW; i += 256) mx = fmaxf(mx, fabsf(q[i]));
    qmax_s[t] = mx;
    __syncthreads();
    for (int s2 = 128; s2 > 0; s2 >>= 1) {
        if (t < s2) qmax_s[t] = fmaxf(qmax_s[t], qmax_s[t + s2]);
        __syncthreads();
    }
    float Qm = fmaxf(qmax_s[0], 1e-20f);
    if (t == 0 && half == 0) g_qmax[c] = Qm;

    // Phase 2: stage tau, log2|tau|, v for this half's 648 j's
    const float* k = reinterpret_cast<const float*>(g_k4) + c * HW + half * JHALF;
    const float* v = reinterpret_cast<const float*>(g_v4) + c * HW + half * JHALF;
    for (int j = t; j < JHALF; j += 256) {
        float tv = k[j] * Qm;
        tau_s[j] = tv;
        lt_s[j]  = __log2f(fabsf(tv));
        v_s[j]   = v[j];
    }
    __syncthreads();

    // Phase 3: accumulate this thread's (m0, m0+1) moments over its 81 j's
    int mp    = t >> 3;      // 0..31 (active < 29)
    int chunk = t & 7;
    if (mp < MPAIRS) {
        int m0 = mp * 2;
        // -log2(m0!) via exact double factorial + exponent extraction
        double fact = 1.0;
        for (int ii = 2; ii <= m0; ii++) fact *= (double)ii;
        long long bb = __double_as_longlong(fact);
        int e2 = (int)((bb >> 52) & 0x7FF) - 1023;
        double mant = __longlong_as_double((bb & 0xFFFFFFFFFFFFFULL) |
                                           0x3FF0000000000000ULL);
        float mlgf = -((float)e2 + __log2f((float)mant));
        float m0f  = (float)m0;
        float inv1 = 1.0f / (float)(m0 + 1);
        bool  is0  = (m0 == 0);

        float S0 = 0.0f, M0 = 0.0f, S1 = 0.0f, M1 = 0.0f;
        int jb = chunk * JCHUNK;
        #pragma unroll 3
        for (int jj = 0; jj < JCHUNK; jj++) {
            float ta = tau_s[jb + jj];
            float lt = lt_s [jb + jj];
            float vv = v_s  [jb + jj];
            float e0 = is0 ? 1.0f : ex2f(fmaf(m0f, lt, mlgf));  // tau^m0/m0! (m0 even -> +)
            float e1 = e0 * (ta * inv1);                        // tau^(m0+1)/(m0+1)!
            S0 += e0; M0 = fmaf(e0, vv, M0);
            S1 += e1; M1 = fmaf(e1, vv, M1);
        }
        red[mp][chunk][0] = S0; red[mp][chunk][1] = M0;
        red[mp][chunk][2] = S1; red[mp][chunk][3] = M1;
    }
    __syncthreads();

    // Phase 4: reduce the 8 chunks; write partial moments for this half
    if (t < MPAIRS * 4) {
        int mp2 = t >> 2, wh = t & 3;
        float s = 0.0f;
        #pragma unroll
        for (int ch2 = 0; ch2 < 8; ch2++) s += red[mp2][ch2][wh];
        int m = mp2 * 2 + (wh >> 1);
        if ((wh & 1) == 0) g_CS[c][half][m] = s;
        else               g_CM[c][half][m] = s;
    }
}

// ---------------------------------------------------------------------------
// Kernel C: per-output dual Horner + gated residual.
//   w = q_i/Qmax in [-1,1];  num = sum_m CM_m w^m;  den = sum_m CS_m w^m
//   out = (g * num/den + yp) / (1+g)
// Coeffs staged in smem (warp-uniform -> LDS broadcast). 114 FMA per output.
// ---------------------------------------------------------------------------
__global__ void eval_kernel(const float* __restrict__ gamma,
                            float* __restrict__ out) {
    __shared__ float cs[NM];
    __shared__ float cm[NM];

    int c = blockIdx.y;
    int t = threadIdx.x;
    if (t < NM) {
        cs[t] = g_CS[c][0][t] + g_CS[c][1][t];
        cm[t] = g_CM[c][0][t] + g_CM[c][1][t];
    }
    __syncthreads();

    int i = blockIdx.x * 256 + t;
    if (i >= HW) return;

    float rQ = 1.0f / g_qmax[c];
    float w  = reinterpret_cast<const float*>(g_q4)[c * HW + i] * rQ;

    float num = cm[NM - 1];
    float den = cs[NM - 1];
    #pragma unroll
    for (int m = NM - 2; m >= 0; m--) {
        num = fmaf(num, w, cm[m]);
        den = fmaf(den, w, cs[m]);
    }

    float gm = __ldg(&gamma[0]);
    float yp = reinterpret_cast<const float*>(g_yp4)[c * HW + i];
    out[c * HW + i] = (gm * (num / den) + yp) / (1.0f + gm);
}

// ---------------------------------------------------------------------------
extern "C" void kernel_launch(void* const* d_in, const int* in_sizes, int n_in,
                              void* d_out, int out_size) {
    const float* x     = (const float*)d_in[0];
    const float* y     = (const float*)d_in[1];
    const float* Wq    = (const float*)d_in[2];
    const float* bq    = (const float*)d_in[3];
    const float* Wk    = (const float*)d_in[4];
    const float* bk    = (const float*)d_in[5];
    const float* Wv    = (const float*)d_in[6];
    const float* bv    = (const float*)d_in[7];
    const float* Wp    = (const float*)d_in[8];
    const float* gamma = (const float*)d_in[9];
    float* out = (float*)d_out;

    proj_kernel<<<(NTOT / 2) / 128, 128>>>(x, y, Wq, bq, Wk, bk, Wv, bv, Wp);

    dim3 mgrid(2, CH);                         // (half, channel)
    moments_kernel<<<mgrid, 256>>>();

    dim3 egrid((HW + 255) / 256, CH);          // (6, 64)
    eval_kernel<<<egrid, 256>>>(gamma, out);
}

// round 11
// speedup vs baseline: 1.5384x; 1.0106x over previous
#include <cuda_runtime.h>
#include <cuda_bf16.h>

// Problem constants
#define CH   64
#define HW   1296
#define NTOT (CH * HW)   // 82944

#define NM      58        // moments m = 0..57
#define MPAIRS  29        // computed as (even, odd) pairs
#define JHALF   648       // j's per moment half-block
#define JCHUNK  81        // j's per moment thread

// Scratch (device globals; float4 forces 16B alignment)
__device__ float4 g_q4 [NTOT / 4];
__device__ float4 g_k4 [NTOT / 4];
__device__ float4 g_v4 [NTOT / 4];
__device__ float4 g_yp4[NTOT / 4];
__device__ float  g_CS[CH][2][64];   // Σ_j τ^m/m!        (denominator moments)
__device__ float  g_CM[CH][2][64];   // Σ_j τ^m/m! v_j    (numerator moments)
__device__ float  g_qmax[CH];

__device__ __forceinline__ float ex2f(float x) {
    float r;
    asm("ex2.approx.f32 %0, %1;" : "=f"(r) : "f"(x));
    return r;
}

// ---------------------------------------------------------------------------
// Kernel A: 1x1-conv projections. One thread = ONE projection x 4 pixels
// (R4/R5 structure: measured ~2.4us vs 14.4us for the pair-fused variant —
// this kernel is LATENCY-bound, so thread count beats traffic reduction).
// p = 0:q  1:k  2:v  3:yp  (p uniform per warp). 2592 warps, 80 LDG/256 FMA.
// ---------------------------------------------------------------------------
__global__ void proj_kernel(const float* __restrict__ x,
                            const float* __restrict__ y,
                            const float* __restrict__ Wq, const float* __restrict__ bq,
                            const float* __restrict__ Wk, const float* __restrict__ bk,
                            const float* __restrict__ Wv, const float* __restrict__ bv,
                            const float* __restrict__ Wp) {
    int g = blockIdx.x * 128 + threadIdx.x;      // 0 .. NTOT-1
    int p = g / (NTOT / 4);                      // projection id
    int r = g - p * (NTOT / 4);
    int o = r / (HW / 4);                        // out channel
    int i = (r - o * (HW / 4)) * 4;              // pixel base

    const float* src;
    const float* Wm;
    float bias;
    if (p == 0)      { src = x; Wm = Wq; bias = __ldg(&bq[o]); }
    else if (p == 1) { src = x; Wm = Wk; bias = __ldg(&bk[o]); }
    else if (p == 2) { src = y; Wm = Wv; bias = __ldg(&bv[o]); }
    else             { src = y; Wm = Wp; bias = 0.0f; }

    float4 acc = make_float4(bias, bias, bias, bias);
    const float4* W4 = reinterpret_cast<const float4*>(Wm + o * CH);

    #pragma unroll 4
    for (int cg = 0; cg < CH / 4; cg++) {
        float4 w = __ldg(&W4[cg]);
        const float* s0 = src + (cg * 4) * HW + i;
        float4 p0 = *reinterpret_cast<const float4*>(s0);
        float4 p1 = *reinterpret_cast<const float4*>(s0 + HW);
        float4 p2 = *reinterpret_cast<const float4*>(s0 + 2 * HW);
        float4 p3 = *reinterpret_cast<const float4*>(s0 + 3 * HW);

        acc.x = fmaf(w.x, p0.x, acc.x); acc.y = fmaf(w.x, p0.y, acc.y);
        acc.z = fmaf(w.x, p0.z, acc.z); acc.w = fmaf(w.x, p0.w, acc.w);
        acc.x = fmaf(w.y, p1.x, acc.x); acc.y = fmaf(w.y, p1.y, acc.y);
        acc.z = fmaf(w.y, p1.z, acc.z); acc.w = fmaf(w.y, p1.w, acc.w);
        acc.x = fmaf(w.z, p2.x, acc.x); acc.y = fmaf(w.z, p2.y, acc.y);
        acc.z = fmaf(w.z, p2.z, acc.z); acc.w = fmaf(w.z, p2.w, acc.w);
        acc.x = fmaf(w.w, p3.x, acc.x); acc.y = fmaf(w.w, p3.y, acc.y);
        acc.z = fmaf(w.w, p3.z, acc.z); acc.w = fmaf(w.w, p3.w, acc.w);
    }

    int idx4 = (o * HW + i) >> 2;
    if (p == 0)      g_q4[idx4] = acc;
    else if (p == 1) g_k4[idx4] = acc;   // raw k (Taylor moments downstream)
    else if (p == 2) g_v4[idx4] = acc;
    else             g_yp4[idx4] = acc;
}

// ---------------------------------------------------------------------------
// Kernel B: per-channel scaled exponential moments.
//   tau_j = k_j * Qmax_c ;  CS_m = sum_j tau^m/m! ;  CM_m = sum_j tau^m/m! v_j
// Grid (2 halves, 64 channels), 256 threads: thread = (m-pair 0..28, chunk 0..7).
// Powers via ex2(m*log2|tau| - log2 m!) for even m (sign +); odd m derived by
// one multiply with the SIGNED tau (automatic sign, /(m+1) folded).
// ---------------------------------------------------------------------------
__global__ void moments_kernel() {
    __shared__ float tau_s[JHALF];
    __shared__ float lt_s [JHALF];
    __shared__ float v_s  [JHALF];
    __shared__ float qmax_s[256];
    __shared__ float red[MPAIRS][8][4];

    int c    = blockIdx.y;
    int half = blockIdx.x;
    int t    = threadIdx.x;

    // Phase 1: Qmax over the full channel's q row
    const float* q = reinterpret_cast<const float*>(g_q4) + c * HW;
    float mx = 0.0f;
    for (int i = t; i < HW; i += 256) mx = fmaxf(mx, fabsf(q[i]));
    qmax_s[t] = mx;
    __syncthreads();
    for (int s2 = 128; s2 > 0; s2 >>= 1) {
        if (t < s2) qmax_s[t] = fmaxf(qmax_s[t], qmax_s[t + s2]);
        __syncthreads();
    }
    float Qm = fmaxf(qmax_s[0], 1e-20f);
    if (t == 0 && half == 0) g_qmax[c] = Qm;

    // Phase 2: stage tau, log2|tau|, v for this half's 648 j's
    const float* k = reinterpret_cast<const float*>(g_k4) + c * HW + half * JHALF;
    const float* v = reinterpret_cast<const float*>(g_v4) + c * HW + half * JHALF;
    for (int j = t; j < JHALF; j += 256) {
        float tv = k[j] * Qm;
        tau_s[j] = tv;
        lt_s[j]  = __log2f(fabsf(tv));
        v_s[j]   = v[j];
    }
    __syncthreads();

    // Phase 3: accumulate this thread's (m0, m0+1) moments over its 81 j's
    int mp    = t >> 3;      // 0..31 (active < 29)
    int chunk = t & 7;
    if (mp < MPAIRS) {
        int m0 = mp * 2;
        // -log2(m0!) via exact double factorial + exponent extraction
        double fact = 1.0;
        for (int ii = 2; ii <= m0; ii++) fact *= (double)ii;
        long long bb = __double_as_longlong(fact);
        int e2 = (int)((bb >> 52) & 0x7FF) - 1023;
        double mant = __longlong_as_double((bb & 0xFFFFFFFFFFFFFULL) |
                                           0x3FF0000000000000ULL);
        float mlgf = -((float)e2 + __log2f((float)mant));
        float m0f  = (float)m0;
        float inv1 = 1.0f / (float)(m0 + 1);
        bool  is0  = (m0 == 0);

        float S0 = 0.0f, M0 = 0.0f, S1 = 0.0f, M1 = 0.0f;
        int jb = chunk * JCHUNK;
        #pragma unroll 3
        for (int jj = 0; jj < JCHUNK; jj++) {
            float ta = tau_s[jb + jj];
            float lt = lt_s [jb + jj];
            float vv = v_s  [jb + jj];
            float e0 = is0 ? 1.0f : ex2f(fmaf(m0f, lt, mlgf));  // tau^m0/m0! (m0 even -> +)
            float e1 = e0 * (ta * inv1);                        // tau^(m0+1)/(m0+1)!
            S0 += e0; M0 = fmaf(e0, vv, M0);
            S1 += e1; M1 = fmaf(e1, vv, M1);
        }
        red[mp][chunk][0] = S0; red[mp][chunk][1] = M0;
        red[mp][chunk][2] = S1; red[mp][chunk][3] = M1;
    }
    __syncthreads();

    // Phase 4: reduce the 8 chunks; write partial moments for this half
    if (t < MPAIRS * 4) {
        int mp2 = t >> 2, wh = t & 3;
        float s = 0.0f;
        #pragma unroll
        for (int ch2 = 0; ch2 < 8; ch2++) s += red[mp2][ch2][wh];
        int m = mp2 * 2 + (wh >> 1);
        if ((wh & 1) == 0) g_CS[c][half][m] = s;
        else               g_CM[c][half][m] = s;
    }
}

// ---------------------------------------------------------------------------
// Kernel C: per-output dual Horner + gated residual.
//   w = q_i/Qmax in [-1,1];  num = sum_m CM_m w^m;  den = sum_m CS_m w^m
//   out = (g * num/den + yp) / (1+g)
// Coeffs staged in smem (warp-uniform -> LDS broadcast). 114 FMA per output.
// ---------------------------------------------------------------------------
__global__ void eval_kernel(const float* __restrict__ gamma,
                            float* __restrict__ out) {
    __shared__ float cs[NM];
    __shared__ float cm[NM];

    int c = blockIdx.y;
    int t = threadIdx.x;
    if (t < NM) {
        cs[t] = g_CS[c][0][t] + g_CS[c][1][t];
        cm[t] = g_CM[c][0][t] + g_CM[c][1][t];
    }
    __syncthreads();

    int i = blockIdx.x * 256 + t;
    if (i >= HW) return;

    float rQ = 1.0f / g_qmax[c];
    float w  = reinterpret_cast<const float*>(g_q4)[c * HW + i] * rQ;

    float num = cm[NM - 1];
    float den = cs[NM - 1];
    #pragma unroll
    for (int m = NM - 2; m >= 0; m--) {
        num = fmaf(num, w, cm[m]);
        den = fmaf(den, w, cs[m]);
    }

    float gm = __ldg(&gamma[0]);
    float yp = reinterpret_cast<const float*>(g_yp4)[c * HW + i];
    out[c * HW + i] = (gm * (num / den) + yp) / (1.0f + gm);
}

// ---------------------------------------------------------------------------
extern "C" void kernel_launch(void* const* d_in, const int* in_sizes, int n_in,
                              void* d_out, int out_size) {
    const float* x     = (const float*)d_in[0];
    const float* y     = (const float*)d_in[1];
    const float* Wq    = (const float*)d_in[2];
    const float* bq    = (const float*)d_in[3];
    const float* Wk    = (const float*)d_in[4];
    const float* bk    = (const float*)d_in[5];
    const float* Wv    = (const float*)d_in[6];
    const float* bv    = (const float*)d_in[7];
    const float* Wp    = (const float*)d_in[8];
    const float* gamma = (const float*)d_in[9];
    float* out = (float*)d_out;

    proj_kernel<<<NTOT / 128, 128>>>(x, y, Wq, bq, Wk, bk, Wv, bv, Wp);

    dim3 mgrid(2, CH);                         // (half, channel)
    moments_kernel<<<mgrid, 256>>>();

    dim3 egrid((HW + 255) / 256, CH);          // (6, 64)
    eval_kernel<<<egrid, 256>>>(gamma, out);
}

// round 12
// speedup vs baseline: 1.8430x; 1.1980x over previous
#include <cuda_runtime.h>
#include <cuda_bf16.h>

// Problem constants
#define CH   64
#define HW   1296
#define NTOT (CH * HW)   // 82944

#define NM      58        // moments m = 0..57
#define MPAIRS  29        // computed as (even, odd) pairs
#define NQ      4         // j quarter-blocks
#define JQ      (HW / NQ) // 324 j's per quarter
#define JCHUNK  81        // j's per moment thread (4 chunks per quarter)

// Scratch (device globals; float4 forces 16B alignment)
__device__ float4 g_q4 [NTOT / 4];
__device__ float4 g_k4 [NTOT / 4];
__device__ float4 g_v4 [NTOT / 4];
__device__ float4 g_yp4[NTOT / 4];
__device__ float  g_CS[CH][NQ][64];  // Σ_j τ^m/m!        (denominator moments)
__device__ float  g_CM[CH][NQ][64];  // Σ_j τ^m/m! v_j    (numerator moments)
__device__ float  g_qmax[CH];

// -log2((2*mp)!) for mp = 0..28  (replaces the serial DP factorial chain)
__constant__ float c_mlgf[MPAIRS] = {
    -0.0f,          -1.0f,          -4.5849625f,   -9.4918531f,
    -15.2992080f,   -21.7910611f,   -28.8354552f,  -36.3432498f,
    -44.2501404f,   -52.5075283f,   -61.0773839f,  -69.9291329f,
    -79.0376574f,   -88.3819533f,   -97.9441957f,  -107.7090673f,
    -117.6632636f,  -127.7951206f,  -138.0943286f, -148.5517095f,
    -159.1590398f,  -169.9089092f,  -180.7946056f, -191.8100206f,
    -202.9495720f,  -214.2081380f,  -225.5810031f, -237.0638110f,
    -248.6525257f
};

__device__ __forceinline__ float ex2f(float x) {
    float r;
    asm("ex2.approx.f32 %0, %1;" : "=f"(r) : "f"(x));
    return r;
}

// ---------------------------------------------------------------------------
// Kernel A: 1x1-conv projections. One thread = ONE projection x 2 pixels.
// 165888 threads -> 5184 warps (~35/SM): latency-bound kernel, so maximize
// warp-level latency hiding (R10/R11 A/B test: traffic reduction was neutral,
// warp count is what moved it).
// ---------------------------------------------------------------------------
__global__ __launch_bounds__(128)
void proj_kernel(const float* __restrict__ x,
                 const float* __restrict__ y,
                 const float* __restrict__ Wq, const float* __restrict__ bq,
                 const float* __restrict__ Wk, const float* __restrict__ bk,
                 const float* __restrict__ Wv, const float* __restrict__ bv,
                 const float* __restrict__ Wp) {
    int g = blockIdx.x * 128 + threadIdx.x;      // 0 .. 165887
    int p = g / (NTOT / 2);                      // projection id 0..3
    int r = g - p * (NTOT / 2);
    int o = r / (HW / 2);                        // out channel
    int i = (r - o * (HW / 2)) * 2;              // pixel base

    const float* src;
    const float* Wm;
    float bias;
    if (p == 0)      { src = x; Wm = Wq; bias = __ldg(&bq[o]); }
    else if (p == 1) { src = x; Wm = Wk; bias = __ldg(&bk[o]); }
    else if (p == 2) { src = y; Wm = Wv; bias = __ldg(&bv[o]); }
    else             { src = y; Wm = Wp; bias = 0.0f; }

    float a0 = bias, a1 = bias;
    const float4* W4 = reinterpret_cast<const float4*>(Wm + o * CH);

    #pragma unroll 4
    for (int cg = 0; cg < CH / 4; cg++) {
        float4 w = __ldg(&W4[cg]);
        const float* s0 = src + (cg * 4) * HW + i;
        float2 p0 = *reinterpret_cast<const float2*>(s0);
        float2 p1 = *reinterpret_cast<const float2*>(s0 + HW);
        float2 p2 = *reinterpret_cast<const float2*>(s0 + 2 * HW);
        float2 p3 = *reinterpret_cast<const float2*>(s0 + 3 * HW);

        a0 = fmaf(w.x, p0.x, a0); a1 = fmaf(w.x, p0.y, a1);
        a0 = fmaf(w.y, p1.x, a0); a1 = fmaf(w.y, p1.y, a1);
        a0 = fmaf(w.z, p2.x, a0); a1 = fmaf(w.z, p2.y, a1);
        a0 = fmaf(w.w, p3.x, a0); a1 = fmaf(w.w, p3.y, a1);
    }

    float2 res = make_float2(a0, a1);
    int idx = o * HW + i;                        // even -> 8B aligned
    if (p == 0)      *reinterpret_cast<float2*>(reinterpret_cast<float*>(g_q4)  + idx) = res;
    else if (p == 1) *reinterpret_cast<float2*>(reinterpret_cast<float*>(g_k4)  + idx) = res;
    else if (p == 2) *reinterpret_cast<float2*>(reinterpret_cast<float*>(g_v4)  + idx) = res;
    else             *reinterpret_cast<float2*>(reinterpret_cast<float*>(g_yp4) + idx) = res;
}

// ---------------------------------------------------------------------------
// Kernel B: per-channel scaled exponential moments.
//   tau_j = k_j * Qmax_c ;  CS_m = sum_j tau^m/m! ;  CM_m = sum_j tau^m/m! v_j
// Grid (4 quarters, 64 channels) = 256 blocks, 128 threads:
// thread = (m-pair 0..28, chunk 0..3), 81 j's per thread.
// Powers via ex2(m*log2|tau| - log2 m!) (table) for even m; odd m derived by
// one multiply with the SIGNED tau (automatic sign, /(m+1) folded).
// ---------------------------------------------------------------------------
__global__ __launch_bounds__(128)
void moments_kernel() {
    __shared__ float tau_s[JQ];
    __shared__ float lt_s [JQ];
    __shared__ float v_s  [JQ];
    __shared__ float qmax_s[4];
    __shared__ float red[MPAIRS][4][4];

    int c    = blockIdx.y;
    int quar = blockIdx.x;
    int t    = threadIdx.x;
    int lane = t & 31;
    int wid  = t >> 5;

    // Phase 1: Qmax over the full channel's q row (warp-shuffle reduce)
    const float* q = reinterpret_cast<const float*>(g_q4) + c * HW;
    float mx = 0.0f;
    for (int i = t; i < HW; i += 128) mx = fmaxf(mx, fabsf(q[i]));
    #pragma unroll
    for (int s2 = 16; s2 > 0; s2 >>= 1)
        mx = fmaxf(mx, __shfl_xor_sync(0xFFFFFFFFu, mx, s2));
    if (lane == 0) qmax_s[wid] = mx;
    __syncthreads();
    float Qm = fmaxf(fmaxf(qmax_s[0], qmax_s[1]),
                     fmaxf(qmax_s[2], qmax_s[3]));
    Qm = fmaxf(Qm, 1e-20f);
    if (t == 0 && quar == 0) g_qmax[c] = Qm;

    // Phase 2: stage tau, log2|tau|, v for this quarter's 324 j's
    const float* k = reinterpret_cast<const float*>(g_k4) + c * HW + quar * JQ;
    const float* v = reinterpret_cast<const float*>(g_v4) + c * HW + quar * JQ;
    for (int j = t; j < JQ; j += 128) {
        float tv = k[j] * Qm;
        tau_s[j] = tv;
        lt_s[j]  = __log2f(fabsf(tv));
        v_s[j]   = v[j];
    }
    __syncthreads();

    // Phase 3: accumulate this thread's (m0, m0+1) moments over its 81 j's
    int mp    = t >> 2;      // 0..31 (active < 29)
    int chunk = t & 3;
    if (mp < MPAIRS) {
        int m0 = mp * 2;
        float mlgf = c_mlgf[mp];
        float m0f  = (float)m0;
        float inv1 = 1.0f / (float)(m0 + 1);
        bool  is0  = (m0 == 0);

        float S0 = 0.0f, M0 = 0.0f, S1 = 0.0f, M1 = 0.0f;
        int jb = chunk * JCHUNK;
        #pragma unroll 3
        for (int jj = 0; jj < JCHUNK; jj++) {
            float ta = tau_s[jb + jj];
            float lt = lt_s [jb + jj];
            float vv = v_s  [jb + jj];
            float e0 = is0 ? 1.0f : ex2f(fmaf(m0f, lt, mlgf));  // tau^m0/m0! (even -> +)
            float e1 = e0 * (ta * inv1);                        // tau^(m0+1)/(m0+1)!
            S0 += e0; M0 = fmaf(e0, vv, M0);
            S1 += e1; M1 = fmaf(e1, vv, M1);
        }
        red[mp][chunk][0] = S0; red[mp][chunk][1] = M0;
        red[mp][chunk][2] = S1; red[mp][chunk][3] = M1;
    }
    __syncthreads();

    // Phase 4: reduce the 4 chunks; write partial moments for this quarter
    if (t < MPAIRS * 4) {
        int mp2 = t >> 2, wh = t & 3;
        float s = 0.0f;
        #pragma unroll
        for (int ch2 = 0; ch2 < 4; ch2++) s += red[mp2][ch2][wh];
        int m = mp2 * 2 + (wh >> 1);
        if ((wh & 1) == 0) g_CS[c][quar][m] = s;
        else               g_CM[c][quar][m] = s;
    }
}

// ---------------------------------------------------------------------------
// Kernel C: per-output dual Horner + gated residual.
//   w = q_i/Qmax in [-1,1];  num = sum_m CM_m w^m;  den = sum_m CS_m w^m
//   out = (g * num/den + yp) / (1+g)
// Coeffs staged in smem (warp-uniform -> LDS broadcast). 114 FMA per output.
// ---------------------------------------------------------------------------
__global__ void eval_kernel(const float* __restrict__ gamma,
                            float* __restrict__ out) {
    __shared__ float cs[NM];
    __shared__ float cm[NM];

    int c = blockIdx.y;
    int t = threadIdx.x;
    if (t < NM) {
        cs[t] = (g_CS[c][0][t] + g_CS[c][1][t]) +
                (g_CS[c][2][t] + g_CS[c][3][t]);
        cm[t] = (g_CM[c][0][t] + g_CM[c][1][t]) +
                (g_CM[c][2][t] + g_CM[c][3][t]);
    }
    __syncthreads();

    int i = blockIdx.x * 256 + t;
    if (i >= HW) return;

    float rQ = 1.0f / g_qmax[c];
    float w  = reinterpret_cast<const float*>(g_q4)[c * HW + i] * rQ;

    float num = cm[NM - 1];
    float den = cs[NM - 1];
    #pragma unroll
    for (int m = NM - 2; m >= 0; m--) {
        num = fmaf(num, w, cm[m]);
        den = fmaf(den, w, cs[m]);
    }

    float gm = __ldg(&gamma[0]);
    float yp = reinterpret_cast<const float*>(g_yp4)[c * HW + i];
    out[c * HW + i] = (gm * (num / den) + yp) / (1.0f + gm);
}

// ---------------------------------------------------------------------------
extern "C" void kernel_launch(void* const* d_in, const int* in_sizes, int n_in,
                              void* d_out, int out_size) {
    const float* x     = (const float*)d_in[0];
    const float* y     = (const float*)d_in[1];
    const float* Wq    = (const float*)d_in[2];
    const float* bq    = (const float*)d_in[3];
    const float* Wk    = (const float*)d_in[4];
    const float* bk    = (const float*)d_in[5];
    const float* Wv    = (const float*)d_in[6];
    const float* bv    = (const float*)d_in[7];
    const float* Wp    = (const float*)d_in[8];
    const float* gamma = (const float*)d_in[9];
    float* out = (float*)d_out;

    proj_kernel<<<(NTOT / 2) * 4 / 128, 128>>>(x, y, Wq, bq, Wk, bk, Wv, bv, Wp);

    dim3 mgrid(NQ, CH);                        // (quarter, channel)
    moments_kernel<<<mgrid, 128>>>();

    dim3 egrid((HW + 255) / 256, CH);          // (6, 64)
    eval_kernel<<<egrid, 256>>>(gamma, out);
}

// round 13
// speedup vs baseline: 2.1753x; 1.1803x over previous
#include <cuda_runtime.h>
#include <cuda_bf16.h>

// Problem constants
#define CH   64
#define HW   1296
#define NTOT (CH * HW)

#define NM      58        // moments m = 0..57
#define MPAIRS  29        // computed as (even, odd) pairs
#define NCHUNK  16        // j-chunks per moment phase
#define JCHUNK  81        // j's per chunk (16*81 = 1296)
#define NT      512       // threads per block

// -log2((2*mp)!) for mp = 0..28
__constant__ float c_mlgf[MPAIRS] = {
    -0.0f,          -1.0f,          -4.5849625f,   -9.4918531f,
    -15.2992080f,   -21.7910611f,   -28.8354552f,  -36.3432498f,
    -44.2501404f,   -52.5075283f,   -61.0773839f,  -69.9291329f,
    -79.0376574f,   -88.3819533f,   -97.9441957f,  -107.7090673f,
    -117.6632636f,  -127.7951206f,  -138.0943286f, -148.5517095f,
    -159.1590398f,  -169.9089092f,  -180.7946056f, -191.8100206f,
    -202.9495720f,  -214.2081380f,  -225.5810031f, -237.0638110f,
    -248.6525257f
};

__device__ __forceinline__ float ex2f(float x) {
    float r;
    asm("ex2.approx.f32 %0, %1;" : "=f"(r) : "f"(x));
    return r;
}

// ---------------------------------------------------------------------------
// ONE kernel, one block per channel (64 blocks x 512 threads).
// Phase 1: projections for channel c only -> x,y read ONCE per block
//          (42 MB total chip traffic, L2-cap bound ~3.7us), results in smem.
// Phase 2: qmax over q row (warp shuffle + smem).
// Phase 3: scaled exponential moments  CS_m = sum_j tau^m/m!,
//          CM_m = sum_j tau^m/m! v_j   (tau = k_j * qmax)
//          thread = (m-pair, j-chunk); powers via ex2(m*log2|tau| - log2 m!).
// Phase 4: chunk reduction -> coefficient arrays cs/cm in smem.
// Phase 5: per-output dual Horner (114 FMA) + gated residual.
// No gmem scratch, no extra launches.
// ---------------------------------------------------------------------------
__global__ __launch_bounds__(NT, 1)
void fused_kernel(const float* __restrict__ x,
                  const float* __restrict__ y,
                  const float* __restrict__ Wq, const float* __restrict__ bq,
                  const float* __restrict__ Wk, const float* __restrict__ bk,
                  const float* __restrict__ Wv, const float* __restrict__ bv,
                  const float* __restrict__ Wp,
                  const float* __restrict__ gamma,
                  float* __restrict__ out) {
    __shared__ float4 wquad[CH];          // (wq, wk, wv, wp) per input channel
    __shared__ float  q_s  [HW];
    __shared__ float  tau_s[HW];          // k, then k*qmax
    __shared__ float  lt_s [HW];          // log2|tau|
    __shared__ float  v_s  [HW];
    __shared__ float  yp_s [HW];
    __shared__ float  qmax_s[NT / 32];
    __shared__ float  red[MPAIRS][NCHUNK][4];
    __shared__ float  cs[NM];
    __shared__ float  cm[NM];

    int c = blockIdx.x;
    int t = threadIdx.x;

    // ---- Phase 0: stage packed weight quads ----
    if (t < CH) {
        wquad[t] = make_float4(__ldg(&Wq[c * CH + t]), __ldg(&Wk[c * CH + t]),
                               __ldg(&Wv[c * CH + t]), __ldg(&Wp[c * CH + t]));
    }
    float bqv = __ldg(&bq[c]);
    float bkv = __ldg(&bk[c]);
    float bvv = __ldg(&bv[c]);
    __syncthreads();

    // ---- Phase 1: projections (pixel-pair per thread iteration) ----
    const float2* x2 = reinterpret_cast<const float2*>(x);
    const float2* y2 = reinterpret_cast<const float2*>(y);
    for (int i2 = t; i2 < HW / 2; i2 += NT) {
        float aq0 = bqv, aq1 = bqv;
        float ak0 = bkv, ak1 = bkv;
        float av0 = bvv, av1 = bvv;
        float ap0 = 0.0f, ap1 = 0.0f;
        #pragma unroll 8
        for (int cp = 0; cp < CH; cp++) {
            float4 w  = wquad[cp];
            float2 xv = __ldg(&x2[cp * (HW / 2) + i2]);
            float2 yv = __ldg(&y2[cp * (HW / 2) + i2]);
            aq0 = fmaf(w.x, xv.x, aq0); aq1 = fmaf(w.x, xv.y, aq1);
            ak0 = fmaf(w.y, xv.x, ak0); ak1 = fmaf(w.y, xv.y, ak1);
            av0 = fmaf(w.z, yv.x, av0); av1 = fmaf(w.z, yv.y, av1);
            ap0 = fmaf(w.w, yv.x, ap0); ap1 = fmaf(w.w, yv.y, ap1);
        }
        int i = i2 * 2;
        q_s  [i] = aq0; q_s  [i + 1] = aq1;
        tau_s[i] = ak0; tau_s[i + 1] = ak1;
        v_s  [i] = av0; v_s  [i + 1] = av1;
        yp_s [i] = ap0; yp_s [i + 1] = ap1;
    }
    __syncthreads();

    // ---- Phase 2: qmax ----
    float mx = 0.0f;
    for (int i = t; i < HW; i += NT) mx = fmaxf(mx, fabsf(q_s[i]));
    #pragma unroll
    for (int s2 = 16; s2 > 0; s2 >>= 1)
        mx = fmaxf(mx, __shfl_xor_sync(0xFFFFFFFFu, mx, s2));
    if ((t & 31) == 0) qmax_s[t >> 5] = mx;
    __syncthreads();
    float Qm = 1e-20f;
    #pragma unroll
    for (int w2 = 0; w2 < NT / 32; w2++) Qm = fmaxf(Qm, qmax_s[w2]);

    // scale tau, compute log2|tau|
    for (int j = t; j < HW; j += NT) {
        float tv = tau_s[j] * Qm;
        tau_s[j] = tv;
        lt_s[j]  = __log2f(fabsf(tv));
    }
    __syncthreads();

    // ---- Phase 3: moments (thread = (m-pair, chunk)) ----
    int mp    = t >> 4;          // 0..31 (active < 29)
    int chunk = t & 15;
    if (mp < MPAIRS) {
        int   m0   = mp * 2;
        float mlgf = c_mlgf[mp];
        float m0f  = (float)m0;
        float inv1 = 1.0f / (float)(m0 + 1);
        bool  is0  = (m0 == 0);

        float S0 = 0.0f, M0 = 0.0f, S1 = 0.0f, M1 = 0.0f;
        int jb = chunk * JCHUNK;
        #pragma unroll 3
        for (int jj = 0; jj < JCHUNK; jj++) {
            float ta = tau_s[jb + jj];
            float lt = lt_s [jb + jj];
            float vv = v_s  [jb + jj];
            float e0 = is0 ? 1.0f : ex2f(fmaf(m0f, lt, mlgf));  // tau^m0/m0!
            float e1 = e0 * (ta * inv1);                        // tau^(m0+1)/(m0+1)!
            S0 += e0; M0 = fmaf(e0, vv, M0);
            S1 += e1; M1 = fmaf(e1, vv, M1);
        }
        red[mp][chunk][0] = S0; red[mp][chunk][1] = M0;
        red[mp][chunk][2] = S1; red[mp][chunk][3] = M1;
    }
    __syncthreads();

    // ---- Phase 4: chunk reduction -> coefficients ----
    if (t < MPAIRS * 4) {
        int mp2 = t >> 2, wh = t & 3;
        float s = 0.0f;
        #pragma unroll
        for (int ch2 = 0; ch2 < NCHUNK; ch2++) s += red[mp2][ch2][wh];
        int m = mp2 * 2 + (wh >> 1);
        if ((wh & 1) == 0) cs[m] = s;
        else               cm[m] = s;
    }
    __syncthreads();

    // ---- Phase 5: dual Horner + gated residual ----
    float gm = __ldg(&gamma[0]);
    float rQ = 1.0f / Qm;
    for (int i = t; i < HW; i += NT) {
        float w = q_s[i] * rQ;
        float num = cm[NM - 1];
        float den = cs[NM - 1];
        #pragma unroll
        for (int m = NM - 2; m >= 0; m--) {
            num = fmaf(num, w, cm[m]);
            den = fmaf(den, w, cs[m]);
        }
        out[c * HW + i] = (gm * (num / den) + yp_s[i]) / (1.0f + gm);
    }
}

// ---------------------------------------------------------------------------
extern "C" void kernel_launch(void* const* d_in, const int* in_sizes, int n_in,
                              void* d_out, int out_size) {
    const float* x     = (const float*)d_in[0];
    const float* y     = (const float*)d_in[1];
    const float* Wq    = (const float*)d_in[2];
    const float* bq    = (const float*)d_in[3];
    const float* Wk    = (const float*)d_in[4];
    const float* bk    = (const float*)d_in[5];
    const float* Wv    = (const float*)d_in[6];
    const float* bv    = (const float*)d_in[7];
    const float* Wp    = (const float*)d_in[8];
    const float* gamma = (const float*)d_in[9];
    float* out = (float*)d_out;

    fused_kernel<<<CH, NT>>>(x, y, Wq, bq, Wk, bk, Wv, bv, Wp, gamma, out);
}